// round 11
// baseline (speedup 1.0000x reference)
#include <cuda_runtime.h>
#include <math.h>

#define B_    256
#define S_    512
#define E_    256
#define H_    512
#define G3_   1536      // 3*H
#define VOCAB_ 32000

// ---------------- device scratch (no allocation allowed) ----------------
__device__ float d_VW[(size_t)VOCAB_ * G3_]; // emb @ Wx^T + b_ih  (196.6 MB)
__device__ float d_WxT [E_ * G3_];           // [k][r] r = g*512+u  (w_ih_w cols 0..255)
__device__ float d_WhT [H_ * G3_];           // w_ih_w cols 256..767 transposed
__device__ float d_WhhT[H_ * G3_];           // w_hh_w transposed
__device__ float d_WipT[H_ * G3_];           // w_ih_p transposed
__device__ float d_WhpT[H_ * G3_];           // w_hh_p transposed
__device__ float d_pinT[H_ * H_];            // pin_w transposed [k][c]
__device__ float d_fusT[2 * H_ * H_];        // fus_w transposed [k (0..1023)][f]
__device__ float d_h1T [H_ * H_];            // h1_w transposed
__device__ float d_hw[2][B_ * H_];           // worker hidden, double buffered
__device__ float d_hp[2][B_ * H_];           // planner hidden, double buffered
__device__ float d_HPP[B_ * G3_];            // hp @ WhT   (refreshed every 4 steps)
__device__ float d_pi [B_ * H_];             // planner input projection
__device__ float d_fused[B_ * H_];
__device__ float d_relu [B_ * H_];

// ---------------- math helpers ----------------
__device__ __forceinline__ float sigf(float x) {
    return 1.0f / (1.0f + __expf(-x));
}
__device__ __forceinline__ float tanh_fast(float x) {
    float ax = fabsf(x);
    float e  = __expf(-2.0f * ax);
    float t  = (1.0f - e) / (1.0f + e);
    return copysignf(t, x);
}

// ---------------- init: zero the recurrent state ----------------
__global__ void init_zero_kernel() {
    int i = blockIdx.x * blockDim.x + threadIdx.x;
    if (i < B_ * H_) { d_hw[0][i] = 0.0f; d_hp[0][i] = 0.0f; }
    if (i < B_ * G3_) d_HPP[i] = 0.0f;
}

// ---------------- transpose all weight matrices (once per launch) ----------------
// dst[k*R + r] = src[r*ld + coff + k], for r<R, k<K
__global__ void transpose_all_kernel(
    const float* __restrict__ wihw, const float* __restrict__ whhw,
    const float* __restrict__ wihp, const float* __restrict__ whhp,
    const float* __restrict__ pinw, const float* __restrict__ fusw,
    const float* __restrict__ h1w)
{
    const float* src; float* dst; int R, K, ld, coff;
    switch (blockIdx.z) {
        case 0: src=wihw; dst=d_WxT;  R=G3_; K=E_;    ld=E_+H_; coff=0;   break;
        case 1: src=wihw; dst=d_WhT;  R=G3_; K=H_;    ld=E_+H_; coff=E_;  break;
        case 2: src=whhw; dst=d_WhhT; R=G3_; K=H_;    ld=H_;    coff=0;   break;
        case 3: src=wihp; dst=d_WipT; R=G3_; K=H_;    ld=H_;    coff=0;   break;
        case 4: src=whhp; dst=d_WhpT; R=G3_; K=H_;    ld=H_;    coff=0;   break;
        case 5: src=pinw; dst=d_pinT; R=H_;  K=H_;    ld=H_;    coff=0;   break;
        case 6: src=fusw; dst=d_fusT; R=H_;  K=2*H_;  ld=2*H_;  coff=0;   break;
        default:src=h1w;  dst=d_h1T;  R=H_;  K=H_;    ld=H_;    coff=0;   break;
    }
    __shared__ float tile[32][33];
    int r0 = blockIdx.y * 32, k0 = blockIdx.x * 32;
    int r = r0 + threadIdx.y, k = k0 + threadIdx.x;
    if (r < R && k < K) tile[threadIdx.y][threadIdx.x] = src[r * ld + coff + k];
    __syncthreads();
    int rr = r0 + threadIdx.x, kk = k0 + threadIdx.y;
    if (rr < R && kk < K) dst[(size_t)kk * R + rr] = tile[threadIdx.x][threadIdx.y];
}

// ---------------- shared 3-gate GEMM core ----------------
// Computes acc[i][g] += sum_k A[m0+ty*4+i][k] * BT[k][g*512 + u0+tx]
// Block: 256 threads (ty = tid>>5 in 0..7 -> 4 rows each; tx = tid&31 -> unit)
// Tile: 32 rows x 32 units (96 cols) x K, BK=16.
__device__ __forceinline__ void gemm3(
    const float* __restrict__ A, int lda,
    const float* __restrict__ BT, int K,
    int m0, int u0, float acc[4][3],
    float* __restrict__ As /*16*33*/, float* __restrict__ Bs /*16*96*/)
{
    int tid = threadIdx.x;
    int tx = tid & 31, ty = tid >> 5;
    for (int k0 = 0; k0 < K; k0 += 16) {
        {
            int k = tid & 15, m = tid >> 4;      // m in 0..15
            As[k * 33 + m]      = A[(m0 + m) * lda + k0 + k];
            As[k * 33 + m + 16] = A[(m0 + m + 16) * lda + k0 + k];
        }
        #pragma unroll
        for (int j = 0; j < 6; j++) {
            int e = tid + 256 * j;               // < 1536
            int k = e / 96, c = e % 96;
            Bs[k * 96 + c] = BT[(size_t)(k0 + k) * G3_ + (c >> 5) * H_ + u0 + (c & 31)];
        }
        __syncthreads();
        #pragma unroll
        for (int k = 0; k < 16; k++) {
            float a0 = As[k * 33 + ty * 4 + 0];
            float a1 = As[k * 33 + ty * 4 + 1];
            float a2 = As[k * 33 + ty * 4 + 2];
            float a3 = As[k * 33 + ty * 4 + 3];
            float br = Bs[k * 96 + tx];
            float bz = Bs[k * 96 + 32 + tx];
            float bn = Bs[k * 96 + 64 + tx];
            acc[0][0] += a0 * br; acc[0][1] += a0 * bz; acc[0][2] += a0 * bn;
            acc[1][0] += a1 * br; acc[1][1] += a1 * bz; acc[1][2] += a1 * bn;
            acc[2][0] += a2 * br; acc[2][1] += a2 * bz; acc[2][2] += a2 * bn;
            acc[3][0] += a3 * br; acc[3][1] += a3 * bz; acc[3][2] += a3 * bn;
        }
        __syncthreads();
    }
}

// ---------------- VW = emb @ Wx^T + b_ih  (whole vocab, once) ----------------
// grid (16, 1000), block 256
__global__ __launch_bounds__(256) void vw_gemm_kernel(
    const float* __restrict__ emb, const float* __restrict__ bihw)
{
    __shared__ float As[16 * 33];
    __shared__ float Bs[16 * 96];
    float acc[4][3] = {};
    int u0 = blockIdx.x * 32, m0 = blockIdx.y * 32;
    gemm3(emb, E_, d_WxT, E_, m0, u0, acc, As, Bs);
    int tx = threadIdx.x & 31, ty = threadIdx.x >> 5;
    int u = u0 + tx;
    float b0 = bihw[u], b1 = bihw[H_ + u], b2 = bihw[2 * H_ + u];
    #pragma unroll
    for (int i = 0; i < 4; i++) {
        size_t m = m0 + ty * 4 + i;
        d_VW[m * G3_ + u]           = acc[i][0] + b0;
        d_VW[m * G3_ + H_ + u]      = acc[i][1] + b1;
        d_VW[m * G3_ + 2 * H_ + u]  = acc[i][2] + b2;
    }
}

// ---------------- worker GRU step (one per t) ----------------
// grid (16, 8), block 256
__global__ __launch_bounds__(256) void worker_step_kernel(
    const int* __restrict__ ids, const int* __restrict__ lens,
    const float* __restrict__ bhh, int t)
{
    __shared__ float As[16 * 33];
    __shared__ float Bs[16 * 96];
    const float* __restrict__ hwin = d_hw[t & 1];
    float* __restrict__ hwout      = d_hw[(t + 1) & 1];
    float acc[4][3] = {};
    int u0 = blockIdx.x * 32, m0 = blockIdx.y * 32;
    gemm3(hwin, H_, d_WhhT, H_, m0, u0, acc, As, Bs);
    int tx = threadIdx.x & 31, ty = threadIdx.x >> 5;
    int u = u0 + tx;
    float bhr = bhh[u], bhz = bhh[H_ + u], bhn = bhh[2 * H_ + u];
    #pragma unroll
    for (int i = 0; i < 4; i++) {
        int m = m0 + ty * 4 + i;
        int id = ids[m * S_ + t];
        const float* vw  = d_VW + (size_t)id * G3_;
        const float* hpp = d_HPP + (size_t)m * G3_;
        float gr = vw[u]          + hpp[u];
        float gz = vw[H_ + u]     + hpp[H_ + u];
        float gn = vw[2 * H_ + u] + hpp[2 * H_ + u];
        float r = sigf(gr + acc[i][0] + bhr);
        float z = sigf(gz + acc[i][1] + bhz);
        float n = tanh_fast(gn + r * (acc[i][2] + bhn));
        float hold = hwin[m * H_ + u];
        float hnew = (1.0f - z) * n + z * hold;
        hwout[m * H_ + u] = (t < lens[m]) ? hnew : hold;
    }
}

// ---------------- planner: pi = hw @ pin^T + pin_b ----------------
// grid (16, 8), block 256   (N tile = 32 cols)
__global__ __launch_bounds__(256) void pi_kernel(const float* __restrict__ pinb, int t)
{
    __shared__ float As[16 * 33];
    __shared__ float Bs[16 * 32];
    const float* __restrict__ hw = d_hw[(t + 1) & 1];
    float acc[4] = {0.f, 0.f, 0.f, 0.f};
    int u0 = blockIdx.x * 32, m0 = blockIdx.y * 32;
    int tid = threadIdx.x, tx = tid & 31, ty = tid >> 5;
    for (int k0 = 0; k0 < H_; k0 += 16) {
        {
            int k = tid & 15, m = tid >> 4;
            As[k * 33 + m]      = hw[(m0 + m) * H_ + k0 + k];
            As[k * 33 + m + 16] = hw[(m0 + m + 16) * H_ + k0 + k];
        }
        {
            #pragma unroll
            for (int j = 0; j < 2; j++) {
                int e = tid + 256 * j;
                int k = e >> 5, c = e & 31;
                Bs[k * 32 + c] = d_pinT[(k0 + k) * H_ + u0 + c];
            }
        }
        __syncthreads();
        #pragma unroll
        for (int k = 0; k < 16; k++) {
            float b = Bs[k * 32 + tx];
            acc[0] += As[k * 33 + ty * 4 + 0] * b;
            acc[1] += As[k * 33 + ty * 4 + 1] * b;
            acc[2] += As[k * 33 + ty * 4 + 2] * b;
            acc[3] += As[k * 33 + ty * 4 + 3] * b;
        }
        __syncthreads();
    }
    int u = u0 + tx;
    float bb = pinb[u];
    #pragma unroll
    for (int i = 0; i < 4; i++) {
        int m = m0 + ty * 4 + i;
        d_pi[m * H_ + u] = acc[i] + bb;
    }
}

// ---------------- planner GRU gates + update ----------------
// grid (16, 8), block 256
__global__ __launch_bounds__(256) void planner_step_kernel(
    const int* __restrict__ lens,
    const float* __restrict__ bip, const float* __restrict__ bhp,
    int t, int p)
{
    __shared__ float As[16 * 33];
    __shared__ float Bs[16 * 96];
    const float* __restrict__ hpin = d_hp[p & 1];
    float* __restrict__ hpout      = d_hp[(p + 1) & 1];
    float acci[4][3] = {};
    float acch[4][3] = {};
    int u0 = blockIdx.x * 32, m0 = blockIdx.y * 32;
    gemm3(d_pi, H_, d_WipT, H_, m0, u0, acci, As, Bs);
    gemm3(hpin, H_, d_WhpT, H_, m0, u0, acch, As, Bs);
    int tx = threadIdx.x & 31, ty = threadIdx.x >> 5;
    int u = u0 + tx;
    float bir = bip[u], biz = bip[H_ + u], bin = bip[2 * H_ + u];
    float bhr = bhp[u], bhz = bhp[H_ + u], bhn = bhp[2 * H_ + u];
    #pragma unroll
    for (int i = 0; i < 4; i++) {
        int m = m0 + ty * 4 + i;
        float r = sigf(acci[i][0] + bir + acch[i][0] + bhr);
        float z = sigf(acci[i][1] + biz + acch[i][1] + bhz);
        float n = tanh_fast(acci[i][2] + bin + r * (acch[i][2] + bhn));
        float hold = hpin[m * H_ + u];
        float hnew = (1.0f - z) * n + z * hold;
        hpout[m * H_ + u] = (t < lens[m]) ? hnew : hold;
    }
}

// ---------------- HPP = hp @ WhT  (refresh after planner update) ----------------
// grid (16, 8), block 256
__global__ __launch_bounds__(256) void hpp_kernel(int p)
{
    __shared__ float As[16 * 33];
    __shared__ float Bs[16 * 96];
    const float* __restrict__ hp = d_hp[(p + 1) & 1];
    float acc[4][3] = {};
    int u0 = blockIdx.x * 32, m0 = blockIdx.y * 32;
    gemm3(hp, H_, d_WhT, H_, m0, u0, acc, As, Bs);
    int tx = threadIdx.x & 31, ty = threadIdx.x >> 5;
    int u = u0 + tx;
    #pragma unroll
    for (int i = 0; i < 4; i++) {
        size_t m = m0 + ty * 4 + i;
        d_HPP[m * G3_ + u]          = acc[i][0];
        d_HPP[m * G3_ + H_ + u]     = acc[i][1];
        d_HPP[m * G3_ + 2 * H_ + u] = acc[i][2];
    }
}

// ---------------- fused = tanh([hw,hp] @ fus^T + fus_b) ----------------
// grid (16, 8), block 256
__global__ __launch_bounds__(256) void fusion_kernel(const float* __restrict__ fusb)
{
    __shared__ float As[16 * 33];
    __shared__ float Bs[16 * 32];
    const float* __restrict__ hw = d_hw[0];
    const float* __restrict__ hp = d_hp[0];
    float acc[4] = {0.f, 0.f, 0.f, 0.f};
    int u0 = blockIdx.x * 32, m0 = blockIdx.y * 32;
    int tid = threadIdx.x, tx = tid & 31, ty = tid >> 5;
    for (int k0 = 0; k0 < 2 * H_; k0 += 16) {
        const float* Asrc = (k0 < H_) ? hw : hp;
        int kb = (k0 < H_) ? k0 : (k0 - H_);
        {
            int k = tid & 15, m = tid >> 4;
            As[k * 33 + m]      = Asrc[(m0 + m) * H_ + kb + k];
            As[k * 33 + m + 16] = Asrc[(m0 + m + 16) * H_ + kb + k];
        }
        {
            #pragma unroll
            for (int j = 0; j < 2; j++) {
                int e = tid + 256 * j;
                int k = e >> 5, c = e & 31;
                Bs[k * 32 + c] = d_fusT[(k0 + k) * H_ + u0 + c];
            }
        }
        __syncthreads();
        #pragma unroll
        for (int k = 0; k < 16; k++) {
            float b = Bs[k * 32 + tx];
            acc[0] += As[k * 33 + ty * 4 + 0] * b;
            acc[1] += As[k * 33 + ty * 4 + 1] * b;
            acc[2] += As[k * 33 + ty * 4 + 2] * b;
            acc[3] += As[k * 33 + ty * 4 + 3] * b;
        }
        __syncthreads();
    }
    int u = u0 + tx;
    float bb = fusb[u];
    #pragma unroll
    for (int i = 0; i < 4; i++) {
        int m = m0 + ty * 4 + i;
        d_fused[m * H_ + u] = tanh_fast(acc[i] + bb);
    }
}

// ---------------- h = relu(fused @ h1^T + h1_b) ----------------
// grid (16, 8), block 256
__global__ __launch_bounds__(256) void h1_kernel(const float* __restrict__ h1b)
{
    __shared__ float As[16 * 33];
    __shared__ float Bs[16 * 32];
    float acc[4] = {0.f, 0.f, 0.f, 0.f};
    int u0 = blockIdx.x * 32, m0 = blockIdx.y * 32;
    int tid = threadIdx.x, tx = tid & 31, ty = tid >> 5;
    for (int k0 = 0; k0 < H_; k0 += 16) {
        {
            int k = tid & 15, m = tid >> 4;
            As[k * 33 + m]      = d_fused[(m0 + m) * H_ + k0 + k];
            As[k * 33 + m + 16] = d_fused[(m0 + m + 16) * H_ + k0 + k];
        }
        {
            #pragma unroll
            for (int j = 0; j < 2; j++) {
                int e = tid + 256 * j;
                int k = e >> 5, c = e & 31;
                Bs[k * 32 + c] = d_h1T[(k0 + k) * H_ + u0 + c];
            }
        }
        __syncthreads();
        #pragma unroll
        for (int k = 0; k < 16; k++) {
            float b = Bs[k * 32 + tx];
            acc[0] += As[k * 33 + ty * 4 + 0] * b;
            acc[1] += As[k * 33 + ty * 4 + 1] * b;
            acc[2] += As[k * 33 + ty * 4 + 2] * b;
            acc[3] += As[k * 33 + ty * 4 + 3] * b;
        }
        __syncthreads();
    }
    int u = u0 + tx;
    float bb = h1b[u];
    #pragma unroll
    for (int i = 0; i < 4; i++) {
        int m = m0 + ty * 4 + i;
        float v = acc[i] + bb;
        d_relu[m * H_ + u] = v > 0.0f ? v : 0.0f;
    }
}

// ---------------- out = h @ h2^T + h2_b ----------------
// grid (B), block 320: one warp per class
__global__ void out_kernel(const float* __restrict__ h2w, const float* __restrict__ h2b,
                           float* __restrict__ out)
{
    int b = blockIdx.x;
    int c = threadIdx.x >> 5;      // 0..9
    int lane = threadIdx.x & 31;
    float s = 0.0f;
    const float* hrow = d_relu + b * H_;
    const float* wrow = h2w + c * H_;
    for (int k = lane; k < H_; k += 32) s += hrow[k] * wrow[k];
    #pragma unroll
    for (int o = 16; o; o >>= 1) s += __shfl_down_sync(0xffffffff, s, o);
    if (lane == 0) out[b * 10 + c] = s + h2b[c];
}

// ---------------- host launcher (graph-capturable, no allocs) ----------------
extern "C" void kernel_launch(void* const* d_in, const int* in_sizes, int n_in,
                              void* d_out, int out_size)
{
    (void)in_sizes; (void)n_in; (void)out_size;
    const int*   ids  = (const int*)  d_in[0];
    const int*   lens = (const int*)  d_in[1];
    const float* emb  = (const float*)d_in[2];
    const float* wihw = (const float*)d_in[3];
    const float* whhw = (const float*)d_in[4];
    const float* bihw = (const float*)d_in[5];
    const float* bhhw = (const float*)d_in[6];
    const float* pinw = (const float*)d_in[7];
    const float* pinb = (const float*)d_in[8];
    const float* wihp = (const float*)d_in[9];
    const float* whhp = (const float*)d_in[10];
    const float* bihp = (const float*)d_in[11];
    const float* bhhp = (const float*)d_in[12];
    const float* fusw = (const float*)d_in[13];
    const float* fusb = (const float*)d_in[14];
    const float* h1w  = (const float*)d_in[15];
    const float* h1b  = (const float*)d_in[16];
    const float* h2w  = (const float*)d_in[17];
    const float* h2b  = (const float*)d_in[18];
    float* out = (float*)d_out;

    // state init (scratch persists across graph replays -> must reset)
    init_zero_kernel<<<(B_ * G3_ + 255) / 256, 256>>>();

    // weight transposes
    transpose_all_kernel<<<dim3(32, 48, 8), dim3(32, 32)>>>(
        wihw, whhw, wihp, whhp, pinw, fusw, h1w);

    // vocab-wide input projection
    vw_gemm_kernel<<<dim3(16, VOCAB_ / 32), 256>>>(emb, bihw);

    // recurrence
    for (int t = 0; t < S_; t++) {
        worker_step_kernel<<<dim3(16, 8), 256>>>(ids, lens, bhhw, t);
        if (((t + 1) & 3) == 0) {
            int p = ((t + 1) >> 2) - 1;          // 0..127
            pi_kernel<<<dim3(16, 8), 256>>>(pinb, t);
            planner_step_kernel<<<dim3(16, 8), 256>>>(lens, bihp, bhhp, t, p);
            hpp_kernel<<<dim3(16, 8), 256>>>(p);
        }
    }

    // head
    fusion_kernel<<<dim3(16, 8), 256>>>(fusb);
    h1_kernel<<<dim3(16, 8), 256>>>(h1b);
    out_kernel<<<B_, 320>>>(h2w, h2b, out);
}

// round 12
// speedup vs baseline: 1.0004x; 1.0004x over previous
#include <cuda_runtime.h>
#include <math.h>

#define B_    256
#define S_    512
#define E_    256
#define H_    512
#define G3_   1536      // 3*H
#define VOCAB_ 32000

// ---------------- device scratch (no allocation allowed) ----------------
__device__ float d_VW[(size_t)VOCAB_ * G3_]; // emb @ Wx^T + b_ih  (196.6 MB)
__device__ float d_WxT [E_ * G3_];           // [k][r] r = g*512+u  (w_ih_w cols 0..255)
__device__ float d_WhT [H_ * G3_];           // w_ih_w cols 256..767 transposed
__device__ float d_WhhT[H_ * G3_];           // w_hh_w transposed
__device__ float d_WipT[H_ * G3_];           // w_ih_p transposed
__device__ float d_WhpT[H_ * G3_];           // w_hh_p transposed
__device__ float d_pinT[H_ * H_];            // pin_w transposed [k][c]
__device__ float d_fusT[2 * H_ * H_];        // fus_w transposed [k (0..1023)][f]
__device__ float d_h1T [H_ * H_];            // h1_w transposed
__device__ float d_hw[2][B_ * H_];           // worker hidden, double buffered
__device__ float d_hp[2][B_ * H_];           // planner hidden, double buffered
__device__ float d_HPP[B_ * G3_];            // hp @ WhT   (refreshed every 4 steps)
__device__ float d_pi [B_ * H_];             // planner input projection
__device__ float d_fused[B_ * H_];
__device__ float d_relu [B_ * H_];

// ---------------- math helpers ----------------
__device__ __forceinline__ float sigf(float x) {
    return 1.0f / (1.0f + __expf(-x));
}
__device__ __forceinline__ float tanh_fast(float x) {
    float ax = fabsf(x);
    float e  = __expf(-2.0f * ax);
    float t  = (1.0f - e) / (1.0f + e);
    return copysignf(t, x);
}

// ---------------- init: zero the recurrent state ----------------
__global__ void init_zero_kernel() {
    int i = blockIdx.x * blockDim.x + threadIdx.x;
    if (i < B_ * H_) { d_hw[0][i] = 0.0f; d_hp[0][i] = 0.0f; }
    if (i < B_ * G3_) d_HPP[i] = 0.0f;
}

// ---------------- transpose all weight matrices (once per launch) ----------------
// dst[k*R + r] = src[r*ld + coff + k], for r<R, k<K
__global__ void transpose_all_kernel(
    const float* __restrict__ wihw, const float* __restrict__ whhw,
    const float* __restrict__ wihp, const float* __restrict__ whhp,
    const float* __restrict__ pinw, const float* __restrict__ fusw,
    const float* __restrict__ h1w)
{
    const float* src; float* dst; int R, K, ld, coff;
    switch (blockIdx.z) {
        case 0: src=wihw; dst=d_WxT;  R=G3_; K=E_;    ld=E_+H_; coff=0;   break;
        case 1: src=wihw; dst=d_WhT;  R=G3_; K=H_;    ld=E_+H_; coff=E_;  break;
        case 2: src=whhw; dst=d_WhhT; R=G3_; K=H_;    ld=H_;    coff=0;   break;
        case 3: src=wihp; dst=d_WipT; R=G3_; K=H_;    ld=H_;    coff=0;   break;
        case 4: src=whhp; dst=d_WhpT; R=G3_; K=H_;    ld=H_;    coff=0;   break;
        case 5: src=pinw; dst=d_pinT; R=H_;  K=H_;    ld=H_;    coff=0;   break;
        case 6: src=fusw; dst=d_fusT; R=H_;  K=2*H_;  ld=2*H_;  coff=0;   break;
        default:src=h1w;  dst=d_h1T;  R=H_;  K=H_;    ld=H_;    coff=0;   break;
    }
    __shared__ float tile[32][33];
    int r0 = blockIdx.y * 32, k0 = blockIdx.x * 32;
    int r = r0 + threadIdx.y, k = k0 + threadIdx.x;
    if (r < R && k < K) tile[threadIdx.y][threadIdx.x] = src[r * ld + coff + k];
    __syncthreads();
    int rr = r0 + threadIdx.x, kk = k0 + threadIdx.y;
    if (rr < R && kk < K) dst[(size_t)kk * R + rr] = tile[threadIdx.x][threadIdx.y];
}

// ---------------- shared 3-gate GEMM core ----------------
// Computes acc[i][g] += sum_k A[m0+ty*4+i][k] * BT[k][g*512 + u0+tx]
// Block: 256 threads (ty = tid>>5 in 0..7 -> 4 rows each; tx = tid&31 -> unit)
// Tile: 32 rows x 32 units (96 cols) x K, BK=16.
__device__ __forceinline__ void gemm3(
    const float* __restrict__ A, int lda,
    const float* __restrict__ BT, int K,
    int m0, int u0, float acc[4][3],
    float* __restrict__ As /*16*33*/, float* __restrict__ Bs /*16*96*/)
{
    int tid = threadIdx.x;
    int tx = tid & 31, ty = tid >> 5;
    for (int k0 = 0; k0 < K; k0 += 16) {
        {
            int k = tid & 15, m = tid >> 4;      // m in 0..15
            As[k * 33 + m]      = A[(m0 + m) * lda + k0 + k];
            As[k * 33 + m + 16] = A[(m0 + m + 16) * lda + k0 + k];
        }
        #pragma unroll
        for (int j = 0; j < 6; j++) {
            int e = tid + 256 * j;               // < 1536
            int k = e / 96, c = e % 96;
            Bs[k * 96 + c] = BT[(size_t)(k0 + k) * G3_ + (c >> 5) * H_ + u0 + (c & 31)];
        }
        __syncthreads();
        #pragma unroll
        for (int k = 0; k < 16; k++) {
            float a0 = As[k * 33 + ty * 4 + 0];
            float a1 = As[k * 33 + ty * 4 + 1];
            float a2 = As[k * 33 + ty * 4 + 2];
            float a3 = As[k * 33 + ty * 4 + 3];
            float br = Bs[k * 96 + tx];
            float bz = Bs[k * 96 + 32 + tx];
            float bn = Bs[k * 96 + 64 + tx];
            acc[0][0] += a0 * br; acc[0][1] += a0 * bz; acc[0][2] += a0 * bn;
            acc[1][0] += a1 * br; acc[1][1] += a1 * bz; acc[1][2] += a1 * bn;
            acc[2][0] += a2 * br; acc[2][1] += a2 * bz; acc[2][2] += a2 * bn;
            acc[3][0] += a3 * br; acc[3][1] += a3 * bz; acc[3][2] += a3 * bn;
        }
        __syncthreads();
    }
}

// ---------------- VW = emb @ Wx^T + b_ih  (whole vocab, once) ----------------
// grid (16, 1000), block 256
__global__ __launch_bounds__(256) void vw_gemm_kernel(
    const float* __restrict__ emb, const float* __restrict__ bihw)
{
    __shared__ float As[16 * 33];
    __shared__ float Bs[16 * 96];
    float acc[4][3] = {};
    int u0 = blockIdx.x * 32, m0 = blockIdx.y * 32;
    gemm3(emb, E_, d_WxT, E_, m0, u0, acc, As, Bs);
    int tx = threadIdx.x & 31, ty = threadIdx.x >> 5;
    int u = u0 + tx;
    float b0 = bihw[u], b1 = bihw[H_ + u], b2 = bihw[2 * H_ + u];
    #pragma unroll
    for (int i = 0; i < 4; i++) {
        size_t m = m0 + ty * 4 + i;
        d_VW[m * G3_ + u]           = acc[i][0] + b0;
        d_VW[m * G3_ + H_ + u]      = acc[i][1] + b1;
        d_VW[m * G3_ + 2 * H_ + u]  = acc[i][2] + b2;
    }
}

// ---------------- worker GRU step (one per t) ----------------
// grid (16, 8), block 256
__global__ __launch_bounds__(256) void worker_step_kernel(
    const int* __restrict__ ids, const int* __restrict__ lens,
    const float* __restrict__ bhh, int t)
{
    __shared__ float As[16 * 33];
    __shared__ float Bs[16 * 96];
    const float* __restrict__ hwin = d_hw[t & 1];
    float* __restrict__ hwout      = d_hw[(t + 1) & 1];
    float acc[4][3] = {};
    int u0 = blockIdx.x * 32, m0 = blockIdx.y * 32;
    gemm3(hwin, H_, d_WhhT, H_, m0, u0, acc, As, Bs);
    int tx = threadIdx.x & 31, ty = threadIdx.x >> 5;
    int u = u0 + tx;
    float bhr = bhh[u], bhz = bhh[H_ + u], bhn = bhh[2 * H_ + u];
    #pragma unroll
    for (int i = 0; i < 4; i++) {
        int m = m0 + ty * 4 + i;
        int id = ids[m * S_ + t];
        const float* vw  = d_VW + (size_t)id * G3_;
        const float* hpp = d_HPP + (size_t)m * G3_;
        float gr = vw[u]          + hpp[u];
        float gz = vw[H_ + u]     + hpp[H_ + u];
        float gn = vw[2 * H_ + u] + hpp[2 * H_ + u];
        float r = sigf(gr + acc[i][0] + bhr);
        float z = sigf(gz + acc[i][1] + bhz);
        float n = tanh_fast(gn + r * (acc[i][2] + bhn));
        float hold = hwin[m * H_ + u];
        float hnew = (1.0f - z) * n + z * hold;
        hwout[m * H_ + u] = (t < lens[m]) ? hnew : hold;
    }
}

// ---------------- planner: pi = hw @ pin^T + pin_b ----------------
// grid (16, 8), block 256   (N tile = 32 cols)
__global__ __launch_bounds__(256) void pi_kernel(const float* __restrict__ pinb, int t)
{
    __shared__ float As[16 * 33];
    __shared__ float Bs[16 * 32];
    const float* __restrict__ hw = d_hw[(t + 1) & 1];
    float acc[4] = {0.f, 0.f, 0.f, 0.f};
    int u0 = blockIdx.x * 32, m0 = blockIdx.y * 32;
    int tid = threadIdx.x, tx = tid & 31, ty = tid >> 5;
    for (int k0 = 0; k0 < H_; k0 += 16) {
        {
            int k = tid & 15, m = tid >> 4;
            As[k * 33 + m]      = hw[(m0 + m) * H_ + k0 + k];
            As[k * 33 + m + 16] = hw[(m0 + m + 16) * H_ + k0 + k];
        }
        {
            #pragma unroll
            for (int j = 0; j < 2; j++) {
                int e = tid + 256 * j;
                int k = e >> 5, c = e & 31;
                Bs[k * 32 + c] = d_pinT[(k0 + k) * H_ + u0 + c];
            }
        }
        __syncthreads();
        #pragma unroll
        for (int k = 0; k < 16; k++) {
            float b = Bs[k * 32 + tx];
            acc[0] += As[k * 33 + ty * 4 + 0] * b;
            acc[1] += As[k * 33 + ty * 4 + 1] * b;
            acc[2] += As[k * 33 + ty * 4 + 2] * b;
            acc[3] += As[k * 33 + ty * 4 + 3] * b;
        }
        __syncthreads();
    }
    int u = u0 + tx;
    float bb = pinb[u];
    #pragma unroll
    for (int i = 0; i < 4; i++) {
        int m = m0 + ty * 4 + i;
        d_pi[m * H_ + u] = acc[i] + bb;
    }
}

// ---------------- planner GRU gates + update ----------------
// grid (16, 8), block 256
__global__ __launch_bounds__(256) void planner_step_kernel(
    const int* __restrict__ lens,
    const float* __restrict__ bip, const float* __restrict__ bhp,
    int t, int p)
{
    __shared__ float As[16 * 33];
    __shared__ float Bs[16 * 96];
    const float* __restrict__ hpin = d_hp[p & 1];
    float* __restrict__ hpout      = d_hp[(p + 1) & 1];
    float acci[4][3] = {};
    float acch[4][3] = {};
    int u0 = blockIdx.x * 32, m0 = blockIdx.y * 32;
    gemm3(d_pi, H_, d_WipT, H_, m0, u0, acci, As, Bs);
    gemm3(hpin, H_, d_WhpT, H_, m0, u0, acch, As, Bs);
    int tx = threadIdx.x & 31, ty = threadIdx.x >> 5;
    int u = u0 + tx;
    float bir = bip[u], biz = bip[H_ + u], bin = bip[2 * H_ + u];
    float bhr = bhp[u], bhz = bhp[H_ + u], bhn = bhp[2 * H_ + u];
    #pragma unroll
    for (int i = 0; i < 4; i++) {
        int m = m0 + ty * 4 + i;
        float r = sigf(acci[i][0] + bir + acch[i][0] + bhr);
        float z = sigf(acci[i][1] + biz + acch[i][1] + bhz);
        float n = tanh_fast(acci[i][2] + bin + r * (acch[i][2] + bhn));
        float hold = hpin[m * H_ + u];
        float hnew = (1.0f - z) * n + z * hold;
        hpout[m * H_ + u] = (t < lens[m]) ? hnew : hold;
    }
}

// ---------------- HPP = hp @ WhT  (refresh after planner update) ----------------
// grid (16, 8), block 256
__global__ __launch_bounds__(256) void hpp_kernel(int p)
{
    __shared__ float As[16 * 33];
    __shared__ float Bs[16 * 96];
    const float* __restrict__ hp = d_hp[(p + 1) & 1];
    float acc[4][3] = {};
    int u0 = blockIdx.x * 32, m0 = blockIdx.y * 32;
    gemm3(hp, H_, d_WhT, H_, m0, u0, acc, As, Bs);
    int tx = threadIdx.x & 31, ty = threadIdx.x >> 5;
    int u = u0 + tx;
    #pragma unroll
    for (int i = 0; i < 4; i++) {
        size_t m = m0 + ty * 4 + i;
        d_HPP[m * G3_ + u]          = acc[i][0];
        d_HPP[m * G3_ + H_ + u]     = acc[i][1];
        d_HPP[m * G3_ + 2 * H_ + u] = acc[i][2];
    }
}

// ---------------- fused = tanh([hw,hp] @ fus^T + fus_b) ----------------
// grid (16, 8), block 256
__global__ __launch_bounds__(256) void fusion_kernel(const float* __restrict__ fusb)
{
    __shared__ float As[16 * 33];
    __shared__ float Bs[16 * 32];
    const float* __restrict__ hw = d_hw[0];
    const float* __restrict__ hp = d_hp[0];
    float acc[4] = {0.f, 0.f, 0.f, 0.f};
    int u0 = blockIdx.x * 32, m0 = blockIdx.y * 32;
    int tid = threadIdx.x, tx = tid & 31, ty = tid >> 5;
    for (int k0 = 0; k0 < 2 * H_; k0 += 16) {
        const float* Asrc = (k0 < H_) ? hw : hp;
        int kb = (k0 < H_) ? k0 : (k0 - H_);
        {
            int k = tid & 15, m = tid >> 4;
            As[k * 33 + m]      = Asrc[(m0 + m) * H_ + kb + k];
            As[k * 33 + m + 16] = Asrc[(m0 + m + 16) * H_ + kb + k];
        }
        {
            #pragma unroll
            for (int j = 0; j < 2; j++) {
                int e = tid + 256 * j;
                int k = e >> 5, c = e & 31;
                Bs[k * 32 + c] = d_fusT[(k0 + k) * H_ + u0 + c];
            }
        }
        __syncthreads();
        #pragma unroll
        for (int k = 0; k < 16; k++) {
            float b = Bs[k * 32 + tx];
            acc[0] += As[k * 33 + ty * 4 + 0] * b;
            acc[1] += As[k * 33 + ty * 4 + 1] * b;
            acc[2] += As[k * 33 + ty * 4 + 2] * b;
            acc[3] += As[k * 33 + ty * 4 + 3] * b;
        }
        __syncthreads();
    }
    int u = u0 + tx;
    float bb = fusb[u];
    #pragma unroll
    for (int i = 0; i < 4; i++) {
        int m = m0 + ty * 4 + i;
        d_fused[m * H_ + u] = tanh_fast(acc[i] + bb);
    }
}

// ---------------- h = relu(fused @ h1^T + h1_b) ----------------
// grid (16, 8), block 256
__global__ __launch_bounds__(256) void h1_kernel(const float* __restrict__ h1b)
{
    __shared__ float As[16 * 33];
    __shared__ float Bs[16 * 32];
    float acc[4] = {0.f, 0.f, 0.f, 0.f};
    int u0 = blockIdx.x * 32, m0 = blockIdx.y * 32;
    int tid = threadIdx.x, tx = tid & 31, ty = tid >> 5;
    for (int k0 = 0; k0 < H_; k0 += 16) {
        {
            int k = tid & 15, m = tid >> 4;
            As[k * 33 + m]      = d_fused[(m0 + m) * H_ + k0 + k];
            As[k * 33 + m + 16] = d_fused[(m0 + m + 16) * H_ + k0 + k];
        }
        {
            #pragma unroll
            for (int j = 0; j < 2; j++) {
                int e = tid + 256 * j;
                int k = e >> 5, c = e & 31;
                Bs[k * 32 + c] = d_h1T[(k0 + k) * H_ + u0 + c];
            }
        }
        __syncthreads();
        #pragma unroll
        for (int k = 0; k < 16; k++) {
            float b = Bs[k * 32 + tx];
            acc[0] += As[k * 33 + ty * 4 + 0] * b;
            acc[1] += As[k * 33 + ty * 4 + 1] * b;
            acc[2] += As[k * 33 + ty * 4 + 2] * b;
            acc[3] += As[k * 33 + ty * 4 + 3] * b;
        }
        __syncthreads();
    }
    int u = u0 + tx;
    float bb = h1b[u];
    #pragma unroll
    for (int i = 0; i < 4; i++) {
        int m = m0 + ty * 4 + i;
        float v = acc[i] + bb;
        d_relu[m * H_ + u] = v > 0.0f ? v : 0.0f;
    }
}

// ---------------- out = h @ h2^T + h2_b ----------------
// grid (B), block 320: one warp per class
__global__ void out_kernel(const float* __restrict__ h2w, const float* __restrict__ h2b,
                           float* __restrict__ out)
{
    int b = blockIdx.x;
    int c = threadIdx.x >> 5;      // 0..9
    int lane = threadIdx.x & 31;
    float s = 0.0f;
    const float* hrow = d_relu + b * H_;
    const float* wrow = h2w + c * H_;
    for (int k = lane; k < H_; k += 32) s += hrow[k] * wrow[k];
    #pragma unroll
    for (int o = 16; o; o >>= 1) s += __shfl_down_sync(0xffffffff, s, o);
    if (lane == 0) out[b * 10 + c] = s + h2b[c];
}

// ---------------- host launcher (graph-capturable, no allocs) ----------------
extern "C" void kernel_launch(void* const* d_in, const int* in_sizes, int n_in,
                              void* d_out, int out_size)
{
    (void)in_sizes; (void)n_in; (void)out_size;
    const int*   ids  = (const int*)  d_in[0];
    const int*   lens = (const int*)  d_in[1];
    const float* emb  = (const float*)d_in[2];
    const float* wihw = (const float*)d_in[3];
    const float* whhw = (const float*)d_in[4];
    const float* bihw = (const float*)d_in[5];
    const float* bhhw = (const float*)d_in[6];
    const float* pinw = (const float*)d_in[7];
    const float* pinb = (const float*)d_in[8];
    const float* wihp = (const float*)d_in[9];
    const float* whhp = (const float*)d_in[10];
    const float* bihp = (const float*)d_in[11];
    const float* bhhp = (const float*)d_in[12];
    const float* fusw = (const float*)d_in[13];
    const float* fusb = (const float*)d_in[14];
    const float* h1w  = (const float*)d_in[15];
    const float* h1b  = (const float*)d_in[16];
    const float* h2w  = (const float*)d_in[17];
    const float* h2b  = (const float*)d_in[18];
    float* out = (float*)d_out;

    // state init (scratch persists across graph replays -> must reset)
    init_zero_kernel<<<(B_ * G3_ + 255) / 256, 256>>>();

    // weight transposes
    transpose_all_kernel<<<dim3(32, 48, 8), dim3(32, 32)>>>(
        wihw, whhw, wihp, whhp, pinw, fusw, h1w);

    // vocab-wide input projection
    vw_gemm_kernel<<<dim3(16, VOCAB_ / 32), 256>>>(emb, bihw);

    // recurrence
    for (int t = 0; t < S_; t++) {
        worker_step_kernel<<<dim3(16, 8), 256>>>(ids, lens, bhhw, t);
        if (((t + 1) & 3) == 0) {
            int p = ((t + 1) >> 2) - 1;          // 0..127
            pi_kernel<<<dim3(16, 8), 256>>>(pinb, t);
            planner_step_kernel<<<dim3(16, 8), 256>>>(lens, bihp, bhhp, t, p);
            hpp_kernel<<<dim3(16, 8), 256>>>(p);
        }
    }

    // head
    fusion_kernel<<<dim3(16, 8), 256>>>(fusb);
    h1_kernel<<<dim3(16, 8), 256>>>(h1b);
    out_kernel<<<B_, 320>>>(h2w, h2b, out);
}

// round 13
// speedup vs baseline: 1.1740x; 1.1735x over previous
#include <cuda_runtime.h>
#include <math.h>

#define B_    256
#define S_    512
#define E_    256
#define H_    512
#define G3_   1536      // 3*H
#define VOCAB_ 32000

// ---------------- device scratch (no allocation allowed) ----------------
__device__ float d_VW[(size_t)VOCAB_ * G3_]; // emb @ Wx^T + b_ih  (196.6 MB)
__device__ float d_WxT [E_ * G3_];           // [k][r], r = g*512+u  (w_ih_w cols 0..255)
__device__ float d_WhT [H_ * G3_];           // w_ih_w cols 256..767 transposed
__device__ float d_WhhT[H_ * G3_];           // w_hh_w transposed
__device__ float d_WipT[H_ * G3_];           // w_ih_p transposed
__device__ float d_WhpT[H_ * G3_];           // w_hh_p transposed
__device__ float d_pinT[H_ * H_];            // pin_w transposed [k][c]
__device__ float d_fusT[2 * H_ * H_];        // fus_w transposed
__device__ float d_h1T [H_ * H_];            // h1_w transposed
__device__ float d_hw[2][B_ * H_];           // worker hidden (permuted space), double buffered
__device__ float d_hp[2][B_ * H_];           // planner hidden (permuted space), double buffered
__device__ float d_HPP[B_ * G3_];            // hp @ WhT (permuted space)
__device__ float d_pi [B_ * H_];             // planner input projection (permuted)
__device__ float d_fused[B_ * H_];
__device__ float d_relu [B_ * H_];
__device__ int   d_perm[B_];                 // sorted-rank -> original batch index
__device__ int   d_lens_s[B_];               // lengths sorted descending

// ---------------- math helpers ----------------
__device__ __forceinline__ float sigf(float x) {
    return 1.0f / (1.0f + __expf(-x));
}
__device__ __forceinline__ float tanh_fast(float x) {
    float ax = fabsf(x);
    float e  = __expf(-2.0f * ax);
    float t  = (1.0f - e) / (1.0f + e);
    return copysignf(t, x);
}
__device__ __forceinline__ unsigned long long pack2(float lo, float hi) {
    unsigned long long r;
    asm("mov.b64 %0, {%1, %2};" : "=l"(r) : "f"(lo), "f"(hi));
    return r;
}
__device__ __forceinline__ float2 unpack2(unsigned long long v) {
    float2 f;
    asm("mov.b64 {%0, %1}, %2;" : "=f"(f.x), "=f"(f.y) : "l"(v));
    return f;
}
// packed fp32 pair FMA: d.lo += a.lo*b.lo ; d.hi += a.hi*b.hi
__device__ __forceinline__ void ffma2(unsigned long long &d,
                                      unsigned long long a, unsigned long long b) {
    asm("fma.rn.f32x2 %0, %1, %2, %0;" : "+l"(d) : "l"(a), "l"(b));
}

// ---------------- init ----------------
__global__ void init_zero_kernel() {
    int i = blockIdx.x * blockDim.x + threadIdx.x;
    if (i < B_ * H_) { d_hw[0][i] = 0.0f; d_hp[0][i] = 0.0f; }
    if (i < B_ * G3_) d_HPP[i] = 0.0f;
}

// ---------------- sort batch rows by descending length (deterministic) ----------------
__global__ void sort_kernel(const int* __restrict__ lens) {
    __shared__ int L[B_];
    int i = threadIdx.x;
    L[i] = lens[i];
    __syncthreads();
    int li = L[i];
    int rank = 0;
    for (int j = 0; j < B_; j++) {
        int lj = L[j];
        if (lj > li || (lj == li && j < i)) rank++;
    }
    d_perm[rank]   = i;
    d_lens_s[rank] = li;
}

// ---------------- transpose all weight matrices ----------------
__global__ void transpose_all_kernel(
    const float* __restrict__ wihw, const float* __restrict__ whhw,
    const float* __restrict__ wihp, const float* __restrict__ whhp,
    const float* __restrict__ pinw, const float* __restrict__ fusw,
    const float* __restrict__ h1w)
{
    const float* src; float* dst; int R, K, ld, coff;
    switch (blockIdx.z) {
        case 0: src=wihw; dst=d_WxT;  R=G3_; K=E_;    ld=E_+H_; coff=0;   break;
        case 1: src=wihw; dst=d_WhT;  R=G3_; K=H_;    ld=E_+H_; coff=E_;  break;
        case 2: src=whhw; dst=d_WhhT; R=G3_; K=H_;    ld=H_;    coff=0;   break;
        case 3: src=wihp; dst=d_WipT; R=G3_; K=H_;    ld=H_;    coff=0;   break;
        case 4: src=whhp; dst=d_WhpT; R=G3_; K=H_;    ld=H_;    coff=0;   break;
        case 5: src=pinw; dst=d_pinT; R=H_;  K=H_;    ld=H_;    coff=0;   break;
        case 6: src=fusw; dst=d_fusT; R=H_;  K=2*H_;  ld=2*H_;  coff=0;   break;
        default:src=h1w;  dst=d_h1T;  R=H_;  K=H_;    ld=H_;    coff=0;   break;
    }
    __shared__ float tile[32][33];
    int r0 = blockIdx.y * 32, k0 = blockIdx.x * 32;
    int r = r0 + threadIdx.y, k = k0 + threadIdx.x;
    if (r < R && k < K) tile[threadIdx.y][threadIdx.x] = src[r * ld + coff + k];
    __syncthreads();
    int rr = r0 + threadIdx.x, kk = k0 + threadIdx.y;
    if (rr < R && kk < K) dst[(size_t)kk * R + rr] = tile[threadIdx.x][threadIdx.y];
}

// ---------------- f32x2 3-gate GEMM core ----------------
// Block 256 threads. Tile: 32 rows (m0..m0+31) x 32 units (u0..u0+31) x 3 gates.
// Thread (tx=tid&31, ty=tid>>5): rows ty*4..ty*4+3 as two f32x2 pairs, unit u0+tx.
// acc[pair][gate]; pair0 = rows (ty*4, ty*4+1), pair1 = rows (ty*4+2, ty*4+3).
// As[k][m] stride 36 (16B-aligned broadcast LDS.128, conflict-free stores).
// Bs[k][g*32+u] stride 96 (scalar LDS.32 per gate, lane-consecutive).
__device__ __forceinline__ void gemm3_core(
    const float* __restrict__ A, int lda,
    const float* __restrict__ BT, int K,
    int m0, int u0,
    unsigned long long acc[2][3],
    float* __restrict__ As /*32*36*/, float* __restrict__ Bs /*32*96*/)
{
    const int tid = threadIdx.x;
    const int tx = tid & 31, ty = tid >> 5;
    const int am  = tid & 31;          // A loader: row
    const int akq = (tid >> 5) << 2;   // A loader: 4 consecutive k
    const int bk  = tid >> 3;          // B loader: k row
    const int boff= (tid & 7) << 2;    // B loader: 4 consecutive units
    for (int k0 = 0; k0 < K; k0 += 32) {
        float4 av  = *(const float4*)(A  + (size_t)(m0 + am) * lda + k0 + akq);
        const float* brow = BT + (size_t)(k0 + bk) * G3_ + u0 + boff;
        float4 bv0 = *(const float4*)(brow);
        float4 bv1 = *(const float4*)(brow + H_);
        float4 bv2 = *(const float4*)(brow + 2 * H_);
        __syncthreads();               // previous compute done before overwrite
        As[(akq + 0) * 36 + am] = av.x;
        As[(akq + 1) * 36 + am] = av.y;
        As[(akq + 2) * 36 + am] = av.z;
        As[(akq + 3) * 36 + am] = av.w;
        *(float4*)(Bs + bk * 96      + boff) = bv0;
        *(float4*)(Bs + bk * 96 + 32 + boff) = bv1;
        *(float4*)(Bs + bk * 96 + 64 + boff) = bv2;
        __syncthreads();
        #pragma unroll
        for (int k = 0; k < 32; k++) {
            double2 ad = *(const double2*)(As + k * 36 + (ty << 2));  // broadcast
            unsigned long long a0 = __double_as_longlong(ad.x);
            unsigned long long a1 = __double_as_longlong(ad.y);
            float br = Bs[k * 96 + tx];
            float bz = Bs[k * 96 + 32 + tx];
            float bn = Bs[k * 96 + 64 + tx];
            unsigned long long brr = pack2(br, br);
            unsigned long long bzz = pack2(bz, bz);
            unsigned long long bnn = pack2(bn, bn);
            ffma2(acc[0][0], a0, brr); ffma2(acc[1][0], a1, brr);
            ffma2(acc[0][1], a0, bzz); ffma2(acc[1][1], a1, bzz);
            ffma2(acc[0][2], a0, bnn); ffma2(acc[1][2], a1, bnn);
        }
    }
}

// ---------------- f32x2 1-output GEMM core, 64-col tile (for pi) ----------------
__device__ __forceinline__ void gemm1_core_64(
    const float* __restrict__ A, const float* __restrict__ BT /*[K][H_]*/,
    int m0, int u0, unsigned long long acc[2][2],
    float* __restrict__ As /*32*36*/, float* __restrict__ Bs /*32*64*/)
{
    const int tid = threadIdx.x;
    const int tx = tid & 31, ty = tid >> 5;
    const int am  = tid & 31;
    const int akq = (tid >> 5) << 2;
    const int bk  = tid >> 3;
    const int boff= (tid & 7) << 2;
    for (int k0 = 0; k0 < H_; k0 += 32) {
        float4 av = *(const float4*)(A + (size_t)(m0 + am) * H_ + k0 + akq);
        const float* brow = BT + (size_t)(k0 + bk) * H_ + u0 + boff;
        float4 b0 = *(const float4*)(brow);
        float4 b1 = *(const float4*)(brow + 32);
        __syncthreads();
        As[(akq + 0) * 36 + am] = av.x;
        As[(akq + 1) * 36 + am] = av.y;
        As[(akq + 2) * 36 + am] = av.z;
        As[(akq + 3) * 36 + am] = av.w;
        *(float4*)(Bs + bk * 64      + boff) = b0;
        *(float4*)(Bs + bk * 64 + 32 + boff) = b1;
        __syncthreads();
        #pragma unroll
        for (int k = 0; k < 32; k++) {
            double2 ad = *(const double2*)(As + k * 36 + (ty << 2));
            unsigned long long a0 = __double_as_longlong(ad.x);
            unsigned long long a1 = __double_as_longlong(ad.y);
            float s0 = Bs[k * 64 + tx];
            float s1 = Bs[k * 64 + 32 + tx];
            unsigned long long p0 = pack2(s0, s0);
            unsigned long long p1 = pack2(s1, s1);
            ffma2(acc[0][0], a0, p0); ffma2(acc[1][0], a1, p0);
            ffma2(acc[0][1], a0, p1); ffma2(acc[1][1], a1, p1);
        }
    }
}

// unpack acc[2][g] into 4 row values
__device__ __forceinline__ void unpack4(const unsigned long long acc[2], float o[4]) {
    float2 v0 = unpack2(acc[0]);
    float2 v1 = unpack2(acc[1]);
    o[0] = v0.x; o[1] = v0.y; o[2] = v1.x; o[3] = v1.y;
}

// ---------------- VW = emb @ Wx^T + b_ih  (whole vocab, once) ----------------
// grid (16, 1000), block 256
__global__ __launch_bounds__(256) void vw_gemm_kernel(
    const float* __restrict__ emb, const float* __restrict__ bihw)
{
    __shared__ __align__(16) float As[32 * 36];
    __shared__ __align__(16) float Bs[32 * 96];
    unsigned long long acc[2][3] = {};
    int u0 = blockIdx.x * 32, m0 = blockIdx.y * 32;
    gemm3_core(emb, E_, d_WxT, E_, m0, u0, acc, As, Bs);
    int tx = threadIdx.x & 31, ty = threadIdx.x >> 5;
    int u = u0 + tx;
    float b0 = bihw[u], b1 = bihw[H_ + u], b2 = bihw[2 * H_ + u];
    float ar[4], az[4], an[4];
    unpack4(acc[0] ? acc[0] : acc[0], ar); // placate nothing; real unpack below
    { // proper unpacks per gate
        unsigned long long g0[2] = {acc[0][0], acc[1][0]}; unpack4(g0, ar);
        unsigned long long g1[2] = {acc[0][1], acc[1][1]}; unpack4(g1, az);
        unsigned long long g2[2] = {acc[0][2], acc[1][2]}; unpack4(g2, an);
    }
    #pragma unroll
    for (int i = 0; i < 4; i++) {
        size_t m = m0 + ty * 4 + i;
        d_VW[m * G3_ + u]          = ar[i] + b0;
        d_VW[m * G3_ + H_ + u]     = az[i] + b1;
        d_VW[m * G3_ + 2 * H_ + u] = an[i] + b2;
    }
}

// ---------------- worker GRU step ----------------
// grid (16, 8), block 256. Permuted row space. Frozen-block early exit.
__global__ __launch_bounds__(256) void worker_step_kernel(
    const int* __restrict__ ids, const float* __restrict__ bhh, int t)
{
    int u0 = blockIdx.x * 32, m0 = blockIdx.y * 32;
    if (d_lens_s[m0] <= t - 2) return;   // all rows frozen, buffers converged
    __shared__ __align__(16) float As[32 * 36];
    __shared__ __align__(16) float Bs[32 * 96];
    const float* __restrict__ hwin = d_hw[t & 1];
    float* __restrict__ hwout      = d_hw[(t + 1) & 1];
    unsigned long long acc[2][3] = {};
    gemm3_core(hwin, H_, d_WhhT, H_, m0, u0, acc, As, Bs);
    int tx = threadIdx.x & 31, ty = threadIdx.x >> 5;
    int u = u0 + tx;
    float bhr = bhh[u], bhz = bhh[H_ + u], bhn = bhh[2 * H_ + u];
    float ar[4], az[4], an[4];
    { unsigned long long g0[2] = {acc[0][0], acc[1][0]}; unpack4(g0, ar);
      unsigned long long g1[2] = {acc[0][1], acc[1][1]}; unpack4(g1, az);
      unsigned long long g2[2] = {acc[0][2], acc[1][2]}; unpack4(g2, an); }
    #pragma unroll
    for (int i = 0; i < 4; i++) {
        int m   = m0 + ty * 4 + i;
        int len = d_lens_s[m];
        int id  = ids[d_perm[m] * S_ + t];
        const float* vw  = d_VW  + (size_t)id * G3_;
        const float* hpp = d_HPP + (size_t)m  * G3_;
        float gr = vw[u]          + hpp[u];
        float gz = vw[H_ + u]     + hpp[H_ + u];
        float gn = vw[2 * H_ + u] + hpp[2 * H_ + u];
        float r  = sigf(gr + ar[i] + bhr);
        float z  = sigf(gz + az[i] + bhz);
        float n  = tanh_fast(gn + r * (an[i] + bhn));
        float hold = hwin[m * H_ + u];
        float hnew = (1.0f - z) * n + z * hold;
        hwout[m * H_ + u] = (t < len) ? hnew : hold;
    }
}

// ---------------- planner: pi = hw @ pin^T + pin_b ----------------
// grid (8, 8), block 256; tile 32 rows x 64 cols
__global__ __launch_bounds__(256) void pi_kernel(const float* __restrict__ pinb, int t)
{
    int u0 = blockIdx.x * 64, m0 = blockIdx.y * 32;
    if (d_lens_s[m0] <= t - 8) return;
    __shared__ __align__(16) float As[32 * 36];
    __shared__ __align__(16) float Bs[32 * 64];
    const float* __restrict__ hw = d_hw[(t + 1) & 1];
    unsigned long long acc[2][2] = {};
    gemm1_core_64(hw, d_pinT, m0, u0, acc, As, Bs);
    int tx = threadIdx.x & 31, ty = threadIdx.x >> 5;
    float a0[4], a1[4];
    { unsigned long long g0[2] = {acc[0][0], acc[1][0]}; unpack4(g0, a0);
      unsigned long long g1[2] = {acc[0][1], acc[1][1]}; unpack4(g1, a1); }
    float bb0 = pinb[u0 + tx], bb1 = pinb[u0 + 32 + tx];
    #pragma unroll
    for (int i = 0; i < 4; i++) {
        int m = m0 + ty * 4 + i;
        d_pi[m * H_ + u0 + tx]      = a0[i] + bb0;
        d_pi[m * H_ + u0 + 32 + tx] = a1[i] + bb1;
    }
}

// ---------------- planner GRU gates + update (both GEMMs fused) ----------------
// grid (16, 8), block 256
__global__ __launch_bounds__(256) void planner_step_kernel(
    const float* __restrict__ bip, const float* __restrict__ bhp, int t, int p)
{
    int u0 = blockIdx.x * 32, m0 = blockIdx.y * 32;
    if (d_lens_s[m0] <= t - 8) return;
    __shared__ __align__(16) float As[32 * 36];
    __shared__ __align__(16) float Bs[32 * 96];
    const float* __restrict__ hpin = d_hp[p & 1];
    float* __restrict__ hpout      = d_hp[(p + 1) & 1];
    unsigned long long acci[2][3] = {};
    unsigned long long acch[2][3] = {};
    gemm3_core(d_pi, H_, d_WipT, H_, m0, u0, acci, As, Bs);
    gemm3_core(hpin, H_, d_WhpT, H_, m0, u0, acch, As, Bs);
    int tx = threadIdx.x & 31, ty = threadIdx.x >> 5;
    int u = u0 + tx;
    float bir = bip[u], biz = bip[H_ + u], bin = bip[2 * H_ + u];
    float bhr = bhp[u], bhz = bhp[H_ + u], bhn = bhp[2 * H_ + u];
    float ir[4], iz[4], in_[4], hr[4], hz[4], hn[4];
    { unsigned long long g[2];
      g[0]=acci[0][0]; g[1]=acci[1][0]; unpack4(g, ir);
      g[0]=acci[0][1]; g[1]=acci[1][1]; unpack4(g, iz);
      g[0]=acci[0][2]; g[1]=acci[1][2]; unpack4(g, in_);
      g[0]=acch[0][0]; g[1]=acch[1][0]; unpack4(g, hr);
      g[0]=acch[0][1]; g[1]=acch[1][1]; unpack4(g, hz);
      g[0]=acch[0][2]; g[1]=acch[1][2]; unpack4(g, hn); }
    #pragma unroll
    for (int i = 0; i < 4; i++) {
        int m   = m0 + ty * 4 + i;
        int len = d_lens_s[m];
        float r = sigf(ir[i] + bir + hr[i] + bhr);
        float z = sigf(iz[i] + biz + hz[i] + bhz);
        float n = tanh_fast(in_[i] + bin + r * (hn[i] + bhn));
        float hold = hpin[m * H_ + u];
        float hnew = (1.0f - z) * n + z * hold;
        hpout[m * H_ + u] = (t < len) ? hnew : hold;
    }
}

// ---------------- HPP = hp @ WhT  (refresh after planner update) ----------------
// grid (16, 8), block 256
__global__ __launch_bounds__(256) void hpp_kernel(int t, int p)
{
    int u0 = blockIdx.x * 32, m0 = blockIdx.y * 32;
    if (d_lens_s[m0] <= t - 8) return;   // hp frozen -> HPP already correct
    __shared__ __align__(16) float As[32 * 36];
    __shared__ __align__(16) float Bs[32 * 96];
    const float* __restrict__ hp = d_hp[(p + 1) & 1];
    unsigned long long acc[2][3] = {};
    gemm3_core(hp, H_, d_WhT, H_, m0, u0, acc, As, Bs);
    int tx = threadIdx.x & 31, ty = threadIdx.x >> 5;
    int u = u0 + tx;
    float ar[4], az[4], an[4];
    { unsigned long long g0[2] = {acc[0][0], acc[1][0]}; unpack4(g0, ar);
      unsigned long long g1[2] = {acc[0][1], acc[1][1]}; unpack4(g1, az);
      unsigned long long g2[2] = {acc[0][2], acc[1][2]}; unpack4(g2, an); }
    #pragma unroll
    for (int i = 0; i < 4; i++) {
        size_t m = m0 + ty * 4 + i;
        d_HPP[m * G3_ + u]          = ar[i];
        d_HPP[m * G3_ + H_ + u]     = az[i];
        d_HPP[m * G3_ + 2 * H_ + u] = an[i];
    }
}

// ---------------- fused = tanh([hw,hp] @ fus^T + fus_b) ----------------
__global__ __launch_bounds__(256) void fusion_kernel(const float* __restrict__ fusb)
{
    __shared__ float As[16 * 33];
    __shared__ float Bs[16 * 32];
    const float* __restrict__ hw = d_hw[0];
    const float* __restrict__ hp = d_hp[0];
    float acc[4] = {0.f, 0.f, 0.f, 0.f};
    int u0 = blockIdx.x * 32, m0 = blockIdx.y * 32;
    int tid = threadIdx.x, tx = tid & 31, ty = tid >> 5;
    for (int k0 = 0; k0 < 2 * H_; k0 += 16) {
        const float* Asrc = (k0 < H_) ? hw : hp;
        int kb = (k0 < H_) ? k0 : (k0 - H_);
        {
            int k = tid & 15, m = tid >> 4;
            As[k * 33 + m]      = Asrc[(m0 + m) * H_ + kb + k];
            As[k * 33 + m + 16] = Asrc[(m0 + m + 16) * H_ + kb + k];
        }
        {
            #pragma unroll
            for (int j = 0; j < 2; j++) {
                int e = tid + 256 * j;
                int k = e >> 5, c = e & 31;
                Bs[k * 32 + c] = d_fusT[(k0 + k) * H_ + u0 + c];
            }
        }
        __syncthreads();
        #pragma unroll
        for (int k = 0; k < 16; k++) {
            float b = Bs[k * 32 + tx];
            acc[0] += As[k * 33 + ty * 4 + 0] * b;
            acc[1] += As[k * 33 + ty * 4 + 1] * b;
            acc[2] += As[k * 33 + ty * 4 + 2] * b;
            acc[3] += As[k * 33 + ty * 4 + 3] * b;
        }
        __syncthreads();
    }
    int u = u0 + tx;
    float bb = fusb[u];
    #pragma unroll
    for (int i = 0; i < 4; i++) {
        int m = m0 + ty * 4 + i;
        d_fused[m * H_ + u] = tanh_fast(acc[i] + bb);
    }
}

// ---------------- h = relu(fused @ h1^T + h1_b) ----------------
__global__ __launch_bounds__(256) void h1_kernel(const float* __restrict__ h1b)
{
    __shared__ float As[16 * 33];
    __shared__ float Bs[16 * 32];
    float acc[4] = {0.f, 0.f, 0.f, 0.f};
    int u0 = blockIdx.x * 32, m0 = blockIdx.y * 32;
    int tid = threadIdx.x, tx = tid & 31, ty = tid >> 5;
    for (int k0 = 0; k0 < H_; k0 += 16) {
        {
            int k = tid & 15, m = tid >> 4;
            As[k * 33 + m]      = d_fused[(m0 + m) * H_ + k0 + k];
            As[k * 33 + m + 16] = d_fused[(m0 + m + 16) * H_ + k0 + k];
        }
        {
            #pragma unroll
            for (int j = 0; j < 2; j++) {
                int e = tid + 256 * j;
                int k = e >> 5, c = e & 31;
                Bs[k * 32 + c] = d_h1T[(k0 + k) * H_ + u0 + c];
            }
        }
        __syncthreads();
        #pragma unroll
        for (int k = 0; k < 16; k++) {
            float b = Bs[k * 32 + tx];
            acc[0] += As[k * 33 + ty * 4 + 0] * b;
            acc[1] += As[k * 33 + ty * 4 + 1] * b;
            acc[2] += As[k * 33 + ty * 4 + 2] * b;
            acc[3] += As[k * 33 + ty * 4 + 3] * b;
        }
        __syncthreads();
    }
    int u = u0 + tx;
    float bb = h1b[u];
    #pragma unroll
    for (int i = 0; i < 4; i++) {
        int m = m0 + ty * 4 + i;
        float v = acc[i] + bb;
        d_relu[m * H_ + u] = v > 0.0f ? v : 0.0f;
    }
}

// ---------------- out = h @ h2^T + h2_b (un-permutes rows) ----------------
__global__ void out_kernel(const float* __restrict__ h2w, const float* __restrict__ h2b,
                           float* __restrict__ out)
{
    int b = blockIdx.x;                 // permuted row
    int c = threadIdx.x >> 5;           // 0..9
    int lane = threadIdx.x & 31;
    float s = 0.0f;
    const float* hrow = d_relu + b * H_;
    const float* wrow = h2w + c * H_;
    for (int k = lane; k < H_; k += 32) s += hrow[k] * wrow[k];
    #pragma unroll
    for (int o = 16; o; o >>= 1) s += __shfl_down_sync(0xffffffff, s, o);
    if (lane == 0) out[d_perm[b] * 10 + c] = s + h2b[c];
}

// ---------------- host launcher (graph-capturable, no allocs) ----------------
extern "C" void kernel_launch(void* const* d_in, const int* in_sizes, int n_in,
                              void* d_out, int out_size)
{
    (void)in_sizes; (void)n_in; (void)out_size;
    const int*   ids  = (const int*)  d_in[0];
    const int*   lens = (const int*)  d_in[1];
    const float* emb  = (const float*)d_in[2];
    const float* wihw = (const float*)d_in[3];
    const float* whhw = (const float*)d_in[4];
    const float* bihw = (const float*)d_in[5];
    const float* bhhw = (const float*)d_in[6];
    const float* pinw = (const float*)d_in[7];
    const float* pinb = (const float*)d_in[8];
    const float* wihp = (const float*)d_in[9];
    const float* whhp = (const float*)d_in[10];
    const float* bihp = (const float*)d_in[11];
    const float* bhhp = (const float*)d_in[12];
    const float* fusw = (const float*)d_in[13];
    const float* fusb = (const float*)d_in[14];
    const float* h1w  = (const float*)d_in[15];
    const float* h1b  = (const float*)d_in[16];
    const float* h2w  = (const float*)d_in[17];
    const float* h2b  = (const float*)d_in[18];
    float* out = (float*)d_out;

    init_zero_kernel<<<(B_ * G3_ + 255) / 256, 256>>>();
    sort_kernel<<<1, B_>>>(lens);
    transpose_all_kernel<<<dim3(32, 48, 8), dim3(32, 32)>>>(
        wihw, whhw, wihp, whhp, pinw, fusw, h1w);
    vw_gemm_kernel<<<dim3(16, VOCAB_ / 32), 256>>>(emb, bihw);

    for (int t = 0; t < S_; t++) {
        worker_step_kernel<<<dim3(16, 8), 256>>>(ids, bhhw, t);
        if (((t + 1) & 3) == 0) {
            int p = ((t + 1) >> 2) - 1;          // 0..127
            pi_kernel<<<dim3(8, 8), 256>>>(pinb, t);
            planner_step_kernel<<<dim3(16, 8), 256>>>(bihp, bhhp, t, p);
            hpp_kernel<<<dim3(16, 8), 256>>>(t, p);
        }
    }

    fusion_kernel<<<dim3(16, 8), 256>>>(fusb);
    h1_kernel<<<dim3(16, 8), 256>>>(h1b);
    out_kernel<<<B_, 320>>>(h2w, h2b, out);
}